// round 2
// baseline (speedup 1.0000x reference)
#include <cuda_runtime.h>
#include <cuda_bf16.h>
#include <math.h>

#define BB 8
#define TT 4096
#define CC 384
#define HH 6
#define FF 64
#define EE 131072
#define DFF 1536
#define BT (BB*TT)            // 32768
#define NSLOPE 0.2f
#define LNEPS 1e-5f

// ---------------- scratch (device globals; no allocation allowed) ------------
__device__ float g_xn [BT*CC];          // LN1 output
__device__ float g_h  [BT*CC];          // GAT projection h
__device__ float g_x1 [BT*CC];          // x + gat_out
__device__ float g_h2 [BT*CC];          // LN2 output
__device__ float g_ffn[(size_t)BT*DFF]; // MLP hidden
__device__ float g_asrc[BT*HH];
__device__ float g_adst[BT*HH];
__device__ int   g_deg [TT];
__device__ int   g_off [TT+1];
__device__ int   g_cur [TT];
__device__ int   g_csr_src[EE+TT];

// ---------------- CSR build (per launch; edge list shared across batch) ------
__global__ void k_zero_deg() {
    int i = blockIdx.x*blockDim.x + threadIdx.x;
    if (i < TT) g_deg[i] = 0;
}

__global__ void k_hist(const int* __restrict__ ei) {
    int e = blockIdx.x*blockDim.x + threadIdx.x;
    if (e < EE) atomicAdd(&g_deg[ei[EE + e]], 1);   // dst row
}

__global__ void k_scan() {   // single block, 1024 threads, 4 nodes each
    __shared__ int s[1024];
    int tid  = threadIdx.x;
    int base = tid*4;
    int v0 = g_deg[base+0] + 1;   // +1 self loop
    int v1 = g_deg[base+1] + 1;
    int v2 = g_deg[base+2] + 1;
    int v3 = g_deg[base+3] + 1;
    s[tid] = v0+v1+v2+v3;
    __syncthreads();
    for (int d = 1; d < 1024; d <<= 1) {
        int t = (tid >= d) ? s[tid-d] : 0;
        __syncthreads();
        s[tid] += t;
        __syncthreads();
    }
    int excl = (tid == 0) ? 0 : s[tid-1];
    int o0 = excl, o1 = o0+v0, o2 = o1+v1, o3 = o2+v2;
    g_off[base+0]=o0; g_off[base+1]=o1; g_off[base+2]=o2; g_off[base+3]=o3;
    g_cur[base+0]=o0; g_cur[base+1]=o1; g_cur[base+2]=o2; g_cur[base+3]=o3;
    if (tid == 1023) g_off[TT] = s[1023];
}

__global__ void k_fill(const int* __restrict__ ei) {
    int i = blockIdx.x*blockDim.x + threadIdx.x;
    if (i < EE) {
        int d = ei[EE + i];
        int p = atomicAdd(&g_cur[d], 1);
        g_csr_src[p] = ei[i];                       // src row
    } else if (i < EE + TT) {
        int t = i - EE;
        int p = atomicAdd(&g_cur[t], 1);
        g_csr_src[p] = t;                           // self loop
    }
}

// ---------------- layer norm: warp per row, 12 elems/lane --------------------
__global__ void __launch_bounds__(256) k_ln(const float* __restrict__ x,
                                            const float* __restrict__ g,
                                            const float* __restrict__ b,
                                            float* __restrict__ out) {
    int row  = blockIdx.x*8 + (threadIdx.x >> 5);
    int lane = threadIdx.x & 31;
    const float* xr = x + (size_t)row*CC;
    float v[12];
    float sum = 0.f;
    #pragma unroll
    for (int i = 0; i < 12; i++) { v[i] = xr[lane + i*32]; sum += v[i]; }
    #pragma unroll
    for (int o = 16; o; o >>= 1) sum += __shfl_xor_sync(0xffffffffu, sum, o);
    float mu  = sum * (1.f/CC);
    float var = 0.f;
    #pragma unroll
    for (int i = 0; i < 12; i++) { float d = v[i]-mu; var += d*d; }
    #pragma unroll
    for (int o = 16; o; o >>= 1) var += __shfl_xor_sync(0xffffffffu, var, o);
    float rs = rsqrtf(var*(1.f/CC) + LNEPS);
    float* orow = out + (size_t)row*CC;
    #pragma unroll
    for (int i = 0; i < 12; i++) {
        int c = lane + i*32;
        orow[c] = (v[i]-mu)*rs*g[c] + b[c];
    }
}

// ---------------- fp32 tiled GEMM: C = A[MxK] @ B[KxN] (+bias,+relu,+res) ----
// BM=BN=64, BK=16, 256 threads, 4x4 micro-tile. All dims divisible.
template<int RELU, int BIAS, int RES>
__global__ void __launch_bounds__(256) k_gemm(const float* __restrict__ A,
                                              const float* __restrict__ Bm,
                                              const float* __restrict__ bias,
                                              const float* __restrict__ res,
                                              float* __restrict__ Cm,
                                              int M, int N, int K) {
    __shared__ float As[16][65];   // [k][m], padded: conflict-free STS/LDS
    __shared__ float Bs[16][64];   // [k][n]
    int tid = threadIdx.x;
    int tx  = tid & 15;            // n group
    int ty  = tid >> 4;            // m group
    int bm  = blockIdx.y * 64;
    int bn  = blockIdx.x * 64;

    float acc[4][4];
    #pragma unroll
    for (int i = 0; i < 4; i++)
        #pragma unroll
        for (int j = 0; j < 4; j++) acc[i][j] = 0.f;

    int ar = tid >> 4, ak = tid & 15;   // A: 64 rows x 16 k
    int br = tid >> 6, bc = tid & 63;   // B: 16 k    x 64 n

    for (int k0 = 0; k0 < K; k0 += 16) {
        #pragma unroll
        for (int i = 0; i < 4; i++)
            As[ak][ar + 16*i] = A[(size_t)(bm + ar + 16*i)*K + k0 + ak];
        #pragma unroll
        for (int i = 0; i < 4; i++)
            Bs[br + 4*i][bc] = Bm[(size_t)(k0 + br + 4*i)*N + bn + bc];
        __syncthreads();
        #pragma unroll
        for (int kk = 0; kk < 16; kk++) {
            float af[4];
            #pragma unroll
            for (int i = 0; i < 4; i++) af[i] = As[kk][ty*4 + i];
            float4 bv = *(const float4*)&Bs[kk][tx*4];
            float bf[4] = {bv.x, bv.y, bv.z, bv.w};
            #pragma unroll
            for (int i = 0; i < 4; i++)
                #pragma unroll
                for (int j = 0; j < 4; j++)
                    acc[i][j] = fmaf(af[i], bf[j], acc[i][j]);
        }
        __syncthreads();
    }

    #pragma unroll
    for (int i = 0; i < 4; i++) {
        int row = bm + ty*4 + i;
        #pragma unroll
        for (int j = 0; j < 4; j++) {
            int col = bn + tx*4 + j;
            float v = acc[i][j];
            if (BIAS) v += bias[col];
            if (RELU) v = fmaxf(v, 0.f);
            if (RES)  v += res[(size_t)row*N + col];
            Cm[(size_t)row*N + col] = v;
        }
    }
}

// ---------------- attention scores: warp per token ---------------------------
__global__ void __launch_bounds__(256) k_att(const float* __restrict__ att_src,
                                             const float* __restrict__ att_dst) {
    int bt   = blockIdx.x*8 + (threadIdx.x >> 5);
    int lane = threadIdx.x & 31;
    const float* hr = g_h + (size_t)bt*CC;
    #pragma unroll
    for (int hh = 0; hh < HH; hh++) {
        float2 hv = *(const float2*)(hr + hh*FF + lane*2);
        float2 as = *(const float2*)(att_src + hh*FF + lane*2);
        float2 ad = *(const float2*)(att_dst + hh*FF + lane*2);
        float ps = hv.x*as.x + hv.y*as.y;
        float pd = hv.x*ad.x + hv.y*ad.y;
        #pragma unroll
        for (int o = 16; o; o >>= 1) {
            ps += __shfl_xor_sync(0xffffffffu, ps, o);
            pd += __shfl_xor_sync(0xffffffffu, pd, o);
        }
        if (lane == 0) {
            g_asrc[bt*HH + hh] = ps;
            g_adst[bt*HH + hh] = pd;
        }
    }
}

// ---------------- GAT aggregate: warp per (b,t,head), online softmax gather --
__global__ void __launch_bounds__(256) k_gat(const float* __restrict__ x,
                                             const float* __restrict__ b_gat,
                                             float* __restrict__ x1) {
    int w    = blockIdx.x*8 + (threadIdx.x >> 5);   // B*T*H warps
    int lane = threadIdx.x & 31;
    int hh = w % HH;
    int bt = w / HH;
    int t  = bt % TT;
    int b  = bt / TT;

    float adst = g_adst[bt*HH + hh];
    int beg = g_off[t], end = g_off[t+1];

    const float* hbase = g_h + (size_t)b*TT*CC;
    const int hoff = hh*FF + lane*2;

    float m = -1e30f, d = 0.f;
    float accx = 0.f, accy = 0.f;
    for (int i = beg; i < end; i++) {
        int s = g_csr_src[i];
        float a = g_asrc[(b*TT + s)*HH + hh] + adst;
        a = (a >= 0.f) ? a : NSLOPE*a;
        float nm = fmaxf(m, a);
        float sc = __expf(m - nm);
        float wv = __expf(a - nm);
        float2 hv = *(const float2*)(hbase + (size_t)s*CC + hoff);
        accx = accx*sc + wv*hv.x;
        accy = accy*sc + wv*hv.y;
        d    = d*sc + wv;
        m    = nm;
    }
    float inv = 1.f/d;
    int c = hh*FF + lane*2;
    size_t o = (size_t)bt*CC + c;
    x1[o]   = x[o]   + accx*inv + b_gat[c];
    x1[o+1] = x[o+1] + accy*inv + b_gat[c+1];
}

// ---------------- launch ----------------------------------------------------
extern "C" void kernel_launch(void* const* d_in, const int* in_sizes, int n_in,
                              void* d_out, int out_size) {
    const float* x       = (const float*)d_in[0];
    const int*   ei      = (const int*)  d_in[1];
    const float* W_gat   = (const float*)d_in[2];
    const float* att_src = (const float*)d_in[3];
    const float* att_dst = (const float*)d_in[4];
    const float* b_gat   = (const float*)d_in[5];
    const float* ln1_g   = (const float*)d_in[6];
    const float* ln1_b   = (const float*)d_in[7];
    const float* ln2_g   = (const float*)d_in[8];
    const float* ln2_b   = (const float*)d_in[9];
    const float* W1      = (const float*)d_in[10];
    const float* b1      = (const float*)d_in[11];
    const float* W2      = (const float*)d_in[12];
    const float* b2      = (const float*)d_in[13];
    float* out = (float*)d_out;

    float* p_xn;  cudaGetSymbolAddress((void**)&p_xn,  g_xn);
    float* p_h;   cudaGetSymbolAddress((void**)&p_h,   g_h);
    float* p_x1;  cudaGetSymbolAddress((void**)&p_x1,  g_x1);
    float* p_h2;  cudaGetSymbolAddress((void**)&p_h2,  g_h2);
    float* p_ffn; cudaGetSymbolAddress((void**)&p_ffn, g_ffn);

    // CSR build (shared across batch)
    k_zero_deg<<<(TT+255)/256, 256>>>();
    k_hist<<<(EE+255)/256, 256>>>(ei);
    k_scan<<<1, 1024>>>();
    k_fill<<<(EE+TT+255)/256, 256>>>(ei);

    // LN1
    k_ln<<<BT/8, 256>>>(x, ln1_g, ln1_b, p_xn);

    // GAT projection: h = xn @ W_gat   [32768 x 384 x 384]
    k_gemm<0,0,0><<<dim3(CC/64, BT/64), 256>>>(p_xn, W_gat, nullptr, nullptr,
                                               p_h, BT, CC, CC);

    // per-token attention scores
    k_att<<<BT/8, 256>>>(att_src, att_dst);

    // gather + online softmax + residual  -> x1
    k_gat<<<(BT*HH)/8, 256>>>(x, b_gat, p_x1);

    // LN2
    k_ln<<<BT/8, 256>>>(p_x1, ln2_g, ln2_b, p_h2);

    // MLP: relu(h2 @ W1 + b1) -> ffn    [32768 x 1536 x 384]
    k_gemm<1,1,0><<<dim3(DFF/64, BT/64), 256>>>(p_h2, W1, b1, nullptr,
                                                p_ffn, BT, DFF, CC);
    // out = ffn @ W2 + b2 + x1          [32768 x 384 x 1536]
    k_gemm<0,1,1><<<dim3(CC/64, BT/64), 256>>>(p_ffn, W2, b2, p_x1,
                                               out, BT, CC, DFF);
}

// round 5
// speedup vs baseline: 2.7472x; 2.7472x over previous
#include <cuda_runtime.h>
#include <cuda_bf16.h>
#include <stdint.h>
#include <math.h>

#define BB 8
#define TT 4096
#define CC 384
#define HH 6
#define FF 64
#define EE 131072
#define DFF 1536
#define BT (BB*TT)            // 32768
#define NSLOPE 0.2f
#define LNEPS 1e-5f

// ---------------- scratch (device globals; no allocation allowed) ------------
__device__ float g_xn [BT*CC];          // LN1 output
__device__ float g_h  [BT*CC];          // GAT projection h
__device__ float g_x1 [BT*CC];          // x + gat_out
__device__ float g_h2 [BT*CC];          // LN2 output
__device__ float g_ffn[(size_t)BT*DFF]; // MLP hidden
__device__ float g_asrc[BT*HH];
__device__ float g_adst[BT*HH];
__device__ int   g_deg [TT];
__device__ int   g_off [TT+1];
__device__ int   g_cur [TT];
__device__ int   g_csr_src[EE+TT];

// ---------------- CSR build (per launch; edge list shared across batch) ------
__global__ void k_zero_deg() {
    int i = blockIdx.x*blockDim.x + threadIdx.x;
    if (i < TT) g_deg[i] = 0;
}

__global__ void k_hist(const int* __restrict__ ei) {
    int e = blockIdx.x*blockDim.x + threadIdx.x;
    if (e < EE) atomicAdd(&g_deg[ei[EE + e]], 1);   // dst row
}

__global__ void k_scan() {   // single block, 1024 threads, 4 nodes each
    __shared__ int s[1024];
    int tid  = threadIdx.x;
    int base = tid*4;
    int v0 = g_deg[base+0] + 1;   // +1 self loop
    int v1 = g_deg[base+1] + 1;
    int v2 = g_deg[base+2] + 1;
    int v3 = g_deg[base+3] + 1;
    s[tid] = v0+v1+v2+v3;
    __syncthreads();
    for (int d = 1; d < 1024; d <<= 1) {
        int t = (tid >= d) ? s[tid-d] : 0;
        __syncthreads();
        s[tid] += t;
        __syncthreads();
    }
    int excl = (tid == 0) ? 0 : s[tid-1];
    int o0 = excl, o1 = o0+v0, o2 = o1+v1, o3 = o2+v2;
    g_off[base+0]=o0; g_off[base+1]=o1; g_off[base+2]=o2; g_off[base+3]=o3;
    g_cur[base+0]=o0; g_cur[base+1]=o1; g_cur[base+2]=o2; g_cur[base+3]=o3;
    if (tid == 1023) g_off[TT] = s[1023];
}

__global__ void k_fill(const int* __restrict__ ei) {
    int i = blockIdx.x*blockDim.x + threadIdx.x;
    if (i < EE) {
        int d = ei[EE + i];
        int p = atomicAdd(&g_cur[d], 1);
        g_csr_src[p] = ei[i];                       // src row
    } else if (i < EE + TT) {
        int t = i - EE;
        int p = atomicAdd(&g_cur[t], 1);
        g_csr_src[p] = t;                           // self loop
    }
}

// ---------------- layer norm: warp per row, 12 elems/lane --------------------
__global__ void __launch_bounds__(256) k_ln(const float* __restrict__ x,
                                            const float* __restrict__ g,
                                            const float* __restrict__ b,
                                            float* __restrict__ out) {
    int row  = blockIdx.x*8 + (threadIdx.x >> 5);
    int lane = threadIdx.x & 31;
    const float* xr = x + (size_t)row*CC;
    float v[12];
    float sum = 0.f;
    #pragma unroll
    for (int i = 0; i < 12; i++) { v[i] = xr[lane + i*32]; sum += v[i]; }
    #pragma unroll
    for (int o = 16; o; o >>= 1) sum += __shfl_xor_sync(0xffffffffu, sum, o);
    float mu  = sum * (1.f/CC);
    float var = 0.f;
    #pragma unroll
    for (int i = 0; i < 12; i++) { float d = v[i]-mu; var += d*d; }
    #pragma unroll
    for (int o = 16; o; o >>= 1) var += __shfl_xor_sync(0xffffffffu, var, o);
    float rs = rsqrtf(var*(1.f/CC) + LNEPS);
    float* orow = out + (size_t)row*CC;
    #pragma unroll
    for (int i = 0; i < 12; i++) {
        int c = lane + i*32;
        orow[c] = (v[i]-mu)*rs*g[c] + b[c];
    }
}

// ---------------- tf32 tensor-core GEMM -------------------------------------
// C[MxN] = A[MxK] @ B[KxN] (+bias,+relu,+res)
// Block tile 128x128x16, 256 threads (8 warps, 2m x 4n), warp tile 64x32.
// mma.sync.m16n8k8 tf32, cp.async double-buffered smem.
__device__ __forceinline__ uint32_t f2tf32(float f) {
    uint32_t r;
    asm("cvt.rna.tf32.f32 %0, %1;" : "=r"(r) : "f"(f));
    return r;
}

#define SA 20     // As row stride (floats): 16 + 4 pad -> conflict-free frags
#define SB 136    // Bs row stride (floats): 128 + 8 pad -> conflict-free frags

template<int RELU, int BIAS, int RES>
__global__ void __launch_bounds__(256) k_gemm_tc(const float* __restrict__ A,
                                                 const float* __restrict__ Bm,
                                                 const float* __restrict__ bias,
                                                 const float* __restrict__ res,
                                                 float* __restrict__ Cm,
                                                 int M, int N, int K) {
    __shared__ float As[2][128*SA];
    __shared__ float Bs[2][16*SB];

    int tid  = threadIdx.x;
    int lane = tid & 31;
    int w    = tid >> 5;
    int g    = lane >> 2;   // group id (0..7)
    int tg   = lane & 3;    // thread in group (0..3)
    int wm   = w & 1;       // warp m index (0..1)
    int wn   = w >> 1;      // warp n index (0..3)
    int bm   = blockIdx.y * 128;
    int bn   = blockIdx.x * 128;

    float c[4][4][4];
    #pragma unroll
    for (int i = 0; i < 4; i++)
        #pragma unroll
        for (int j = 0; j < 4; j++)
            #pragma unroll
            for (int k = 0; k < 4; k++) c[i][j][k] = 0.f;

    auto loadTile = [&](int k0, int buf) {
        {
            int idx = tid;
            int row = idx >> 2, kc = (idx & 3) * 4;
            uint32_t s = (uint32_t)__cvta_generic_to_shared(&As[buf][row*SA + kc]);
            const float* gp = A + (size_t)(bm + row)*K + k0 + kc;
            asm volatile("cp.async.cg.shared.global [%0], [%1], 16;\n" :: "r"(s), "l"(gp));
            idx = tid + 256;
            row = idx >> 2; kc = (idx & 3) * 4;
            s = (uint32_t)__cvta_generic_to_shared(&As[buf][row*SA + kc]);
            gp = A + (size_t)(bm + row)*K + k0 + kc;
            asm volatile("cp.async.cg.shared.global [%0], [%1], 16;\n" :: "r"(s), "l"(gp));
        }
        {
            int idx = tid;
            int kr = idx >> 5, nc = (idx & 31) * 4;
            uint32_t s = (uint32_t)__cvta_generic_to_shared(&Bs[buf][kr*SB + nc]);
            const float* gp = Bm + (size_t)(k0 + kr)*N + bn + nc;
            asm volatile("cp.async.cg.shared.global [%0], [%1], 16;\n" :: "r"(s), "l"(gp));
            idx = tid + 256;
            kr = idx >> 5; nc = (idx & 31) * 4;
            s = (uint32_t)__cvta_generic_to_shared(&Bs[buf][kr*SB + nc]);
            gp = Bm + (size_t)(k0 + kr)*N + bn + nc;
            asm volatile("cp.async.cg.shared.global [%0], [%1], 16;\n" :: "r"(s), "l"(gp));
        }
        asm volatile("cp.async.commit_group;\n");
    };

    int nk = K / 16;
    loadTile(0, 0);

    for (int i = 0; i < nk; i++) {
        int cur = i & 1;
        asm volatile("cp.async.wait_group 0;\n" ::: "memory");
        __syncthreads();
        if (i + 1 < nk) loadTile((i + 1)*16, (i + 1) & 1);

        const float* Ab = &As[cur][0];
        const float* Bb = &Bs[cur][0];
        #pragma unroll
        for (int ks = 0; ks < 2; ks++) {
            uint32_t a[4][4], b[4][2];
            #pragma unroll
            for (int mi = 0; mi < 4; mi++) {
                int r0 = wm*64 + mi*16 + g;
                a[mi][0] = f2tf32(Ab[ r0    *SA + ks*8 + tg    ]);
                a[mi][1] = f2tf32(Ab[(r0+8) *SA + ks*8 + tg    ]);
                a[mi][2] = f2tf32(Ab[ r0    *SA + ks*8 + tg + 4]);
                a[mi][3] = f2tf32(Ab[(r0+8) *SA + ks*8 + tg + 4]);
            }
            #pragma unroll
            for (int ni = 0; ni < 4; ni++) {
                int cc = wn*32 + ni*8 + g;
                b[ni][0] = f2tf32(Bb[(ks*8 + tg    )*SB + cc]);
                b[ni][1] = f2tf32(Bb[(ks*8 + tg + 4)*SB + cc]);
            }
            #pragma unroll
            for (int mi = 0; mi < 4; mi++)
                #pragma unroll
                for (int ni = 0; ni < 4; ni++)
                    asm volatile(
                        "mma.sync.aligned.m16n8k8.row.col.f32.tf32.tf32.f32 "
                        "{%0,%1,%2,%3}, {%4,%5,%6,%7}, {%8,%9}, {%0,%1,%2,%3};"
                        : "+f"(c[mi][ni][0]), "+f"(c[mi][ni][1]),
                          "+f"(c[mi][ni][2]), "+f"(c[mi][ni][3])
                        : "r"(a[mi][0]), "r"(a[mi][1]), "r"(a[mi][2]), "r"(a[mi][3]),
                          "r"(b[ni][0]), "r"(b[ni][1]));
        }
    }

    // epilogue
    #pragma unroll
    for (int mi = 0; mi < 4; mi++) {
        #pragma unroll
        for (int ni = 0; ni < 4; ni++) {
            int row = bm + wm*64 + mi*16 + g;
            int col = bn + wn*32 + ni*8 + tg*2;
            float bx = 0.f, by = 0.f;
            if (BIAS) { float2 bv = *(const float2*)&bias[col]; bx = bv.x; by = bv.y; }
            float v0 = c[mi][ni][0] + bx;
            float v1 = c[mi][ni][1] + by;
            float v2 = c[mi][ni][2] + bx;
            float v3 = c[mi][ni][3] + by;
            if (RELU) {
                v0 = fmaxf(v0, 0.f); v1 = fmaxf(v1, 0.f);
                v2 = fmaxf(v2, 0.f); v3 = fmaxf(v3, 0.f);
            }
            if (RES) {
                float2 r0 = *(const float2*)&res[(size_t)row*N + col];
                float2 r1 = *(const float2*)&res[(size_t)(row+8)*N + col];
                v0 += r0.x; v1 += r0.y; v2 += r1.x; v3 += r1.y;
            }
            float2 o0 = make_float2(v0, v1);
            float2 o1 = make_float2(v2, v3);
            *(float2*)&Cm[(size_t)row*N + col]     = o0;
            *(float2*)&Cm[(size_t)(row+8)*N + col] = o1;
        }
    }
}

// ---------------- attention scores: warp per token ---------------------------
__global__ void __launch_bounds__(256) k_att(const float* __restrict__ att_src,
                                             const float* __restrict__ att_dst) {
    int bt   = blockIdx.x*8 + (threadIdx.x >> 5);
    int lane = threadIdx.x & 31;
    const float* hr = g_h + (size_t)bt*CC;
    #pragma unroll
    for (int hh = 0; hh < HH; hh++) {
        float2 hv = *(const float2*)(hr + hh*FF + lane*2);
        float2 as = *(const float2*)(att_src + hh*FF + lane*2);
        float2 ad = *(const float2*)(att_dst + hh*FF + lane*2);
        float ps = hv.x*as.x + hv.y*as.y;
        float pd = hv.x*ad.x + hv.y*ad.y;
        #pragma unroll
        for (int o = 16; o; o >>= 1) {
            ps += __shfl_xor_sync(0xffffffffu, ps, o);
            pd += __shfl_xor_sync(0xffffffffu, pd, o);
        }
        if (lane == 0) {
            g_asrc[bt*HH + hh] = ps;
            g_adst[bt*HH + hh] = pd;
        }
    }
}

// ---------------- GAT aggregate: warp per (b,t,head), online softmax gather --
__global__ void __launch_bounds__(256) k_gat(const float* __restrict__ x,
                                             const float* __restrict__ b_gat,
                                             float* __restrict__ x1) {
    int w    = blockIdx.x*8 + (threadIdx.x >> 5);   // B*T*H warps
    int lane = threadIdx.x & 31;
    int hh = w % HH;
    int bt = w / HH;
    int t  = bt % TT;
    int b  = bt / TT;

    float adst = g_adst[bt*HH + hh];
    int beg = g_off[t], end = g_off[t+1];

    const float* hbase = g_h + (size_t)b*TT*CC;
    const int hoff = hh*FF + lane*2;

    float m = -1e30f, d = 0.f;
    float accx = 0.f, accy = 0.f;
    for (int i = beg; i < end; i++) {
        int s = g_csr_src[i];
        float a = g_asrc[(b*TT + s)*HH + hh] + adst;
        a = (a >= 0.f) ? a : NSLOPE*a;
        float nm = fmaxf(m, a);
        float sc = __expf(m - nm);
        float wv = __expf(a - nm);
        float2 hv = *(const float2*)(hbase + (size_t)s*CC + hoff);
        accx = accx*sc + wv*hv.x;
        accy = accy*sc + wv*hv.y;
        d    = d*sc + wv;
        m    = nm;
    }
    float inv = 1.f/d;
    int c = hh*FF + lane*2;
    size_t o = (size_t)bt*CC + c;
    x1[o]   = x[o]   + accx*inv + b_gat[c];
    x1[o+1] = x[o+1] + accy*inv + b_gat[c+1];
}

// ---------------- launch ----------------------------------------------------
extern "C" void kernel_launch(void* const* d_in, const int* in_sizes, int n_in,
                              void* d_out, int out_size) {
    const float* x       = (const float*)d_in[0];
    const int*   ei      = (const int*)  d_in[1];
    const float* W_gat   = (const float*)d_in[2];
    const float* att_src = (const float*)d_in[3];
    const float* att_dst = (const float*)d_in[4];
    const float* b_gat   = (const float*)d_in[5];
    const float* ln1_g   = (const float*)d_in[6];
    const float* ln1_b   = (const float*)d_in[7];
    const float* ln2_g   = (const float*)d_in[8];
    const float* ln2_b   = (const float*)d_in[9];
    const float* W1      = (const float*)d_in[10];
    const float* b1      = (const float*)d_in[11];
    const float* W2      = (const float*)d_in[12];
    const float* b2      = (const float*)d_in[13];
    float* out = (float*)d_out;

    float* p_xn;  cudaGetSymbolAddress((void**)&p_xn,  g_xn);
    float* p_h;   cudaGetSymbolAddress((void**)&p_h,   g_h);
    float* p_x1;  cudaGetSymbolAddress((void**)&p_x1,  g_x1);
    float* p_h2;  cudaGetSymbolAddress((void**)&p_h2,  g_h2);
    float* p_ffn; cudaGetSymbolAddress((void**)&p_ffn, g_ffn);

    // CSR build (shared across batch)
    k_zero_deg<<<(TT+255)/256, 256>>>();
    k_hist<<<(EE+255)/256, 256>>>(ei);
    k_scan<<<1, 1024>>>();
    k_fill<<<(EE+TT+255)/256, 256>>>(ei);

    // LN1
    k_ln<<<BT/8, 256>>>(x, ln1_g, ln1_b, p_xn);

    // GAT projection: h = xn @ W_gat   [32768 x 384 x 384]
    k_gemm_tc<0,0,0><<<dim3(CC/128, BT/128), 256>>>(p_xn, W_gat, nullptr, nullptr,
                                                    p_h, BT, CC, CC);

    // per-token attention scores
    k_att<<<BT/8, 256>>>(att_src, att_dst);

    // gather + online softmax + residual  -> x1
    k_gat<<<(BT*HH)/8, 256>>>(x, b_gat, p_x1);

    // LN2
    k_ln<<<BT/8, 256>>>(p_x1, ln2_g, ln2_b, p_h2);

    // MLP: relu(h2 @ W1 + b1) -> ffn    [32768 x 1536 x 384]
    k_gemm_tc<1,1,0><<<dim3(DFF/128, BT/128), 256>>>(p_h2, W1, b1, nullptr,
                                                     p_ffn, BT, DFF, CC);
    // out = ffn @ W2 + b2 + x1          [32768 x 384 x 1536]
    k_gemm_tc<0,1,1><<<dim3(CC/128, BT/128), 256>>>(p_ffn, W2, b2, p_x1,
                                                    out, BT, CC, DFF);
}

// round 6
// speedup vs baseline: 3.1069x; 1.1309x over previous
#include <cuda_runtime.h>
#include <cuda_bf16.h>
#include <stdint.h>
#include <math.h>

#define BB 8
#define TT 4096
#define CC 384
#define HH 6
#define FF 64
#define EE 131072
#define DFF 1536
#define BT (BB*TT)            // 32768
#define NSLOPE 0.2f
#define LNEPS 1e-5f

// ---------------- scratch (device globals; no allocation allowed) ------------
__device__ float g_xn [BT*CC];          // LN1 output (tf32-rounded)
__device__ float g_h  [BT*CC];          // GAT projection h (full fp32)
__device__ float g_x1 [BT*CC];          // x + gat_out
__device__ float g_h2 [BT*CC];          // LN2 output (tf32-rounded)
__device__ float g_ffn[(size_t)BT*DFF]; // MLP hidden (tf32-rounded)
__device__ float g_wg_t[CC*CC];         // tf32-rounded weights
__device__ float g_w1_t[CC*DFF];
__device__ float g_w2_t[DFF*CC];
__device__ float g_asrc[BT*HH];
__device__ float g_adst[BT*HH];
__device__ int   g_deg [TT];
__device__ int   g_off [TT+1];
__device__ int   g_cur [TT];
__device__ int   g_csr_src[EE+TT];

__device__ __forceinline__ uint32_t f2tf32(float f) {
    uint32_t r;
    asm("cvt.rna.tf32.f32 %0, %1;" : "=r"(r) : "f"(f));
    return r;
}
__device__ __forceinline__ float f2tf32f(float f) {
    return __uint_as_float(f2tf32(f));
}

// ---------------- weight tf32 pre-round --------------------------------------
__global__ void k_cvt(const float* __restrict__ in, float* __restrict__ out, int n4) {
    int i = blockIdx.x*blockDim.x + threadIdx.x;
    if (i < n4) {
        float4 v = ((const float4*)in)[i];
        v.x = f2tf32f(v.x); v.y = f2tf32f(v.y);
        v.z = f2tf32f(v.z); v.w = f2tf32f(v.w);
        ((float4*)out)[i] = v;
    }
}

// ---------------- CSR build (per launch; edge list shared across batch) ------
__global__ void k_zero_deg() {
    int i = blockIdx.x*blockDim.x + threadIdx.x;
    if (i < TT) g_deg[i] = 0;
}

__global__ void k_hist(const int* __restrict__ ei) {
    int e = blockIdx.x*blockDim.x + threadIdx.x;
    if (e < EE) atomicAdd(&g_deg[ei[EE + e]], 1);   // dst row
}

__global__ void k_scan() {   // single block, 1024 threads, 4 nodes each
    __shared__ int s[1024];
    int tid  = threadIdx.x;
    int base = tid*4;
    int v0 = g_deg[base+0] + 1;   // +1 self loop
    int v1 = g_deg[base+1] + 1;
    int v2 = g_deg[base+2] + 1;
    int v3 = g_deg[base+3] + 1;
    s[tid] = v0+v1+v2+v3;
    __syncthreads();
    for (int d = 1; d < 1024; d <<= 1) {
        int t = (tid >= d) ? s[tid-d] : 0;
        __syncthreads();
        s[tid] += t;
        __syncthreads();
    }
    int excl = (tid == 0) ? 0 : s[tid-1];
    int o0 = excl, o1 = o0+v0, o2 = o1+v1, o3 = o2+v2;
    g_off[base+0]=o0; g_off[base+1]=o1; g_off[base+2]=o2; g_off[base+3]=o3;
    g_cur[base+0]=o0; g_cur[base+1]=o1; g_cur[base+2]=o2; g_cur[base+3]=o3;
    if (tid == 1023) g_off[TT] = s[1023];
}

__global__ void k_fill(const int* __restrict__ ei) {
    int i = blockIdx.x*blockDim.x + threadIdx.x;
    if (i < EE) {
        int d = ei[EE + i];
        int p = atomicAdd(&g_cur[d], 1);
        g_csr_src[p] = ei[i];                       // src row
    } else if (i < EE + TT) {
        int t = i - EE;
        int p = atomicAdd(&g_cur[t], 1);
        g_csr_src[p] = t;                           // self loop
    }
}

// ---------------- layer norm: warp per row, 12 elems/lane --------------------
// ROUND: store tf32-rounded output (feeds a tensor-core GEMM as A)
template<int ROUND>
__global__ void __launch_bounds__(256) k_ln(const float* __restrict__ x,
                                            const float* __restrict__ g,
                                            const float* __restrict__ b,
                                            float* __restrict__ out) {
    int row  = blockIdx.x*8 + (threadIdx.x >> 5);
    int lane = threadIdx.x & 31;
    const float* xr = x + (size_t)row*CC;
    float v[12];
    float sum = 0.f;
    #pragma unroll
    for (int i = 0; i < 12; i++) { v[i] = xr[lane + i*32]; sum += v[i]; }
    #pragma unroll
    for (int o = 16; o; o >>= 1) sum += __shfl_xor_sync(0xffffffffu, sum, o);
    float mu  = sum * (1.f/CC);
    float var = 0.f;
    #pragma unroll
    for (int i = 0; i < 12; i++) { float d = v[i]-mu; var += d*d; }
    #pragma unroll
    for (int o = 16; o; o >>= 1) var += __shfl_xor_sync(0xffffffffu, var, o);
    float rs = rsqrtf(var*(1.f/CC) + LNEPS);
    float* orow = out + (size_t)row*CC;
    #pragma unroll
    for (int i = 0; i < 12; i++) {
        int c = lane + i*32;
        float o = (v[i]-mu)*rs*g[c] + b[c];
        orow[c] = ROUND ? f2tf32f(o) : o;
    }
}

// ---------------- tf32 tensor-core GEMM -------------------------------------
// C[MxN] = A[MxK] @ B[KxN] (+bias,+relu,+res,+tf32-round-output)
// Operands PRE-ROUNDED to tf32 -> mainloop is LDS+HMMA only.
// Block tile 128x128x16, 256 threads (8 warps, 2m x 4n), warp tile 64x32.
#define SA 20     // As row stride (floats): 16 + 4 pad
#define SB 136    // Bs row stride (floats): 128 + 8 pad

template<int RELU, int BIAS, int RES, int CVTOUT>
__global__ void __launch_bounds__(256) k_gemm_tc(const float* __restrict__ A,
                                                 const float* __restrict__ Bm,
                                                 const float* __restrict__ bias,
                                                 const float* __restrict__ res,
                                                 float* __restrict__ Cm,
                                                 int M, int N, int K) {
    __shared__ float As[2][128*SA];
    __shared__ float Bs[2][16*SB];

    int tid  = threadIdx.x;
    int lane = tid & 31;
    int w    = tid >> 5;
    int g    = lane >> 2;   // group id (0..7)
    int tg   = lane & 3;    // thread in group (0..3)
    int wm   = w & 1;       // warp m index (0..1)
    int wn   = w >> 1;      // warp n index (0..3)
    int bm   = blockIdx.y * 128;
    int bn   = blockIdx.x * 128;

    float c[4][4][4];
    #pragma unroll
    for (int i = 0; i < 4; i++)
        #pragma unroll
        for (int j = 0; j < 4; j++)
            #pragma unroll
            for (int k = 0; k < 4; k++) c[i][j][k] = 0.f;

    auto loadTile = [&](int k0, int buf) {
        {
            int idx = tid;
            int row = idx >> 2, kc = (idx & 3) * 4;
            uint32_t s = (uint32_t)__cvta_generic_to_shared(&As[buf][row*SA + kc]);
            const float* gp = A + (size_t)(bm + row)*K + k0 + kc;
            asm volatile("cp.async.cg.shared.global [%0], [%1], 16;\n" :: "r"(s), "l"(gp));
            idx = tid + 256;
            row = idx >> 2; kc = (idx & 3) * 4;
            s = (uint32_t)__cvta_generic_to_shared(&As[buf][row*SA + kc]);
            gp = A + (size_t)(bm + row)*K + k0 + kc;
            asm volatile("cp.async.cg.shared.global [%0], [%1], 16;\n" :: "r"(s), "l"(gp));
        }
        {
            int idx = tid;
            int kr = idx >> 5, nc = (idx & 31) * 4;
            uint32_t s = (uint32_t)__cvta_generic_to_shared(&Bs[buf][kr*SB + nc]);
            const float* gp = Bm + (size_t)(k0 + kr)*N + bn + nc;
            asm volatile("cp.async.cg.shared.global [%0], [%1], 16;\n" :: "r"(s), "l"(gp));
            idx = tid + 256;
            kr = idx >> 5; nc = (idx & 31) * 4;
            s = (uint32_t)__cvta_generic_to_shared(&Bs[buf][kr*SB + nc]);
            gp = Bm + (size_t)(k0 + kr)*N + bn + nc;
            asm volatile("cp.async.cg.shared.global [%0], [%1], 16;\n" :: "r"(s), "l"(gp));
        }
        asm volatile("cp.async.commit_group;\n");
    };

    int nk = K / 16;
    loadTile(0, 0);

    for (int i = 0; i < nk; i++) {
        int cur = i & 1;
        asm volatile("cp.async.wait_group 0;\n" ::: "memory");
        __syncthreads();
        if (i + 1 < nk) loadTile((i + 1)*16, (i + 1) & 1);

        const float* Ab = &As[cur][0];
        const float* Bb = &Bs[cur][0];
        #pragma unroll
        for (int ks = 0; ks < 2; ks++) {
            uint32_t a[4][4], b[4][2];
            #pragma unroll
            for (int mi = 0; mi < 4; mi++) {
                int r0 = wm*64 + mi*16 + g;
                a[mi][0] = __float_as_uint(Ab[ r0    *SA + ks*8 + tg    ]);
                a[mi][1] = __float_as_uint(Ab[(r0+8) *SA + ks*8 + tg    ]);
                a[mi][2] = __float_as_uint(Ab[ r0    *SA + ks*8 + tg + 4]);
                a[mi][3] = __float_as_uint(Ab[(r0+8) *SA + ks*8 + tg + 4]);
            }
            #pragma unroll
            for (int ni = 0; ni < 4; ni++) {
                int cc = wn*32 + ni*8 + g;
                b[ni][0] = __float_as_uint(Bb[(ks*8 + tg    )*SB + cc]);
                b[ni][1] = __float_as_uint(Bb[(ks*8 + tg + 4)*SB + cc]);
            }
            #pragma unroll
            for (int mi = 0; mi < 4; mi++)
                #pragma unroll
                for (int ni = 0; ni < 4; ni++)
                    asm volatile(
                        "mma.sync.aligned.m16n8k8.row.col.f32.tf32.tf32.f32 "
                        "{%0,%1,%2,%3}, {%4,%5,%6,%7}, {%8,%9}, {%0,%1,%2,%3};"
                        : "+f"(c[mi][ni][0]), "+f"(c[mi][ni][1]),
                          "+f"(c[mi][ni][2]), "+f"(c[mi][ni][3])
                        : "r"(a[mi][0]), "r"(a[mi][1]), "r"(a[mi][2]), "r"(a[mi][3]),
                          "r"(b[ni][0]), "r"(b[ni][1]));
        }
    }

    // epilogue
    #pragma unroll
    for (int mi = 0; mi < 4; mi++) {
        #pragma unroll
        for (int ni = 0; ni < 4; ni++) {
            int row = bm + wm*64 + mi*16 + g;
            int col = bn + wn*32 + ni*8 + tg*2;
            float bx = 0.f, by = 0.f;
            if (BIAS) { float2 bv = *(const float2*)&bias[col]; bx = bv.x; by = bv.y; }
            float v0 = c[mi][ni][0] + bx;
            float v1 = c[mi][ni][1] + by;
            float v2 = c[mi][ni][2] + bx;
            float v3 = c[mi][ni][3] + by;
            if (RELU) {
                v0 = fmaxf(v0, 0.f); v1 = fmaxf(v1, 0.f);
                v2 = fmaxf(v2, 0.f); v3 = fmaxf(v3, 0.f);
            }
            if (RES) {
                float2 r0 = *(const float2*)&res[(size_t)row*N + col];
                float2 r1 = *(const float2*)&res[(size_t)(row+8)*N + col];
                v0 += r0.x; v1 += r0.y; v2 += r1.x; v3 += r1.y;
            }
            if (CVTOUT) {
                v0 = f2tf32f(v0); v1 = f2tf32f(v1);
                v2 = f2tf32f(v2); v3 = f2tf32f(v3);
            }
            float2 o0 = make_float2(v0, v1);
            float2 o1 = make_float2(v2, v3);
            *(float2*)&Cm[(size_t)row*N + col]     = o0;
            *(float2*)&Cm[(size_t)(row+8)*N + col] = o1;
        }
    }
}

// ---------------- attention scores: warp per token ---------------------------
__global__ void __launch_bounds__(256) k_att(const float* __restrict__ att_src,
                                             const float* __restrict__ att_dst) {
    int bt   = blockIdx.x*8 + (threadIdx.x >> 5);
    int lane = threadIdx.x & 31;
    const float* hr = g_h + (size_t)bt*CC;
    #pragma unroll
    for (int hh = 0; hh < HH; hh++) {
        float2 hv = *(const float2*)(hr + hh*FF + lane*2);
        float2 as = *(const float2*)(att_src + hh*FF + lane*2);
        float2 ad = *(const float2*)(att_dst + hh*FF + lane*2);
        float ps = hv.x*as.x + hv.y*as.y;
        float pd = hv.x*ad.x + hv.y*ad.y;
        #pragma unroll
        for (int o = 16; o; o >>= 1) {
            ps += __shfl_xor_sync(0xffffffffu, ps, o);
            pd += __shfl_xor_sync(0xffffffffu, pd, o);
        }
        if (lane == 0) {
            g_asrc[bt*HH + hh] = ps;
            g_adst[bt*HH + hh] = pd;
        }
    }
}

// ---------------- GAT aggregate: ONE warp per (b,t), all 6 heads -------------
// lane covers cols {j*128 + lane*4 .. +3} for j=0..2; each float4 lies fully in
// head h_j = j*2 + (lane>=16)  ->  3 online-softmax states per lane, no shuffles.
__global__ void __launch_bounds__(256) k_gat(const float* __restrict__ x,
                                             const float* __restrict__ b_gat,
                                             float* __restrict__ x1) {
    int w    = blockIdx.x*8 + (threadIdx.x >> 5);   // bt index in [0,BT)
    int lane = threadIdx.x & 31;
    int t = w % TT;
    int b = w / TT;
    int half = lane >> 4;                           // 0 or 1
    int colbase = (lane & 15)*4 + half*64;          // wait: see below

    // heads for this lane: h_j = j*2 + half, cols j*128 + lane*4
    // lane*4 in [0,124]; head-of-col = (lane*4)/64 + j*2 = j*2 + (lane>=16). OK:
    int cb = lane*4;

    float adst[3];
    #pragma unroll
    for (int j = 0; j < 3; j++) adst[j] = g_adst[w*HH + j*2 + half];

    int beg = g_off[t], end = g_off[t+1];
    const float* hbase = g_h + (size_t)b*TT*CC;
    const float* asrcb = g_asrc + (size_t)b*TT*HH;

    float4 acc[3];
    #pragma unroll
    for (int j = 0; j < 3; j++) acc[j] = make_float4(0.f,0.f,0.f,0.f);
    float m[3] = {-1e30f,-1e30f,-1e30f};
    float d[3] = {0.f,0.f,0.f};

    for (int i = beg; i < end; i++) {
        int s = g_csr_src[i];
        const float* hrow = hbase + (size_t)s*CC;
        const float* arow = asrcb + s*HH;
        #pragma unroll
        for (int j = 0; j < 3; j++) {
            float a = arow[j*2 + half] + adst[j];
            a = (a >= 0.f) ? a : NSLOPE*a;
            float nm = fmaxf(m[j], a);
            float sc = __expf(m[j] - nm);
            float wv = __expf(a - nm);
            float4 hv = *(const float4*)(hrow + j*128 + cb);
            acc[j].x = acc[j].x*sc + wv*hv.x;
            acc[j].y = acc[j].y*sc + wv*hv.y;
            acc[j].z = acc[j].z*sc + wv*hv.z;
            acc[j].w = acc[j].w*sc + wv*hv.w;
            d[j] = d[j]*sc + wv;
            m[j] = nm;
        }
    }

    #pragma unroll
    for (int j = 0; j < 3; j++) {
        float inv = 1.f/d[j];
        int col = j*128 + cb;
        size_t o = (size_t)w*CC + col;
        float4 xv = *(const float4*)(x + o);
        float4 bg = *(const float4*)(b_gat + col);
        float4 r;
        r.x = xv.x + acc[j].x*inv + bg.x;
        r.y = xv.y + acc[j].y*inv + bg.y;
        r.z = xv.z + acc[j].z*inv + bg.z;
        r.w = xv.w + acc[j].w*inv + bg.w;
        *(float4*)(x1 + o) = r;
    }
}

// ---------------- launch ----------------------------------------------------
extern "C" void kernel_launch(void* const* d_in, const int* in_sizes, int n_in,
                              void* d_out, int out_size) {
    const float* x       = (const float*)d_in[0];
    const int*   ei      = (const int*)  d_in[1];
    const float* W_gat   = (const float*)d_in[2];
    const float* att_src = (const float*)d_in[3];
    const float* att_dst = (const float*)d_in[4];
    const float* b_gat   = (const float*)d_in[5];
    const float* ln1_g   = (const float*)d_in[6];
    const float* ln1_b   = (const float*)d_in[7];
    const float* ln2_g   = (const float*)d_in[8];
    const float* ln2_b   = (const float*)d_in[9];
    const float* W1      = (const float*)d_in[10];
    const float* b1      = (const float*)d_in[11];
    const float* W2      = (const float*)d_in[12];
    const float* b2      = (const float*)d_in[13];
    float* out = (float*)d_out;

    float* p_xn;  cudaGetSymbolAddress((void**)&p_xn,  g_xn);
    float* p_h;   cudaGetSymbolAddress((void**)&p_h,   g_h);
    float* p_x1;  cudaGetSymbolAddress((void**)&p_x1,  g_x1);
    float* p_h2;  cudaGetSymbolAddress((void**)&p_h2,  g_h2);
    float* p_ffn; cudaGetSymbolAddress((void**)&p_ffn, g_ffn);
    float* p_wg;  cudaGetSymbolAddress((void**)&p_wg,  g_wg_t);
    float* p_w1;  cudaGetSymbolAddress((void**)&p_w1,  g_w1_t);
    float* p_w2;  cudaGetSymbolAddress((void**)&p_w2,  g_w2_t);

    // weight tf32 pre-round
    k_cvt<<<(CC*CC/4+255)/256, 256>>>(W_gat, p_wg, CC*CC/4);
    k_cvt<<<(CC*DFF/4+255)/256, 256>>>(W1, p_w1, CC*DFF/4);
    k_cvt<<<(DFF*CC/4+255)/256, 256>>>(W2, p_w2, DFF*CC/4);

    // CSR build (shared across batch)
    k_zero_deg<<<(TT+255)/256, 256>>>();
    k_hist<<<(EE+255)/256, 256>>>(ei);
    k_scan<<<1, 1024>>>();
    k_fill<<<(EE+TT+255)/256, 256>>>(ei);

    // LN1 (tf32-rounded output, feeds GEMM1 A)
    k_ln<1><<<BT/8, 256>>>(x, ln1_g, ln1_b, p_xn);

    // GAT projection: h = xn @ W_gat   [32768 x 384 x 384]
    k_gemm_tc<0,0,0,0><<<dim3(CC/128, BT/128), 256>>>(p_xn, p_wg, nullptr, nullptr,
                                                      p_h, BT, CC, CC);

    // per-token attention scores
    k_att<<<BT/8, 256>>>(att_src, att_dst);

    // gather + online softmax + residual  -> x1  (one warp per (b,t))
    k_gat<<<BT/8, 256>>>(x, b_gat, p_x1);

    // LN2 (tf32-rounded output, feeds GEMM2 A)
    k_ln<1><<<BT/8, 256>>>(p_x1, ln2_g, ln2_b, p_h2);

    // MLP: relu(h2 @ W1 + b1) -> ffn (tf32-rounded, feeds GEMM3 A)
    k_gemm_tc<1,1,0,1><<<dim3(DFF/128, BT/128), 256>>>(p_h2, p_w1, b1, nullptr,
                                                       p_ffn, BT, DFF, CC);
    // out = ffn @ W2 + b2 + x1          [32768 x 384 x 1536]
    k_gemm_tc<0,1,1,0><<<dim3(CC/128, BT/128), 256>>>(p_ffn, p_w2, b2, p_x1,
                                                      out, BT, CC, DFF);
}